// round 9
// baseline (speedup 1.0000x reference)
#include <cuda_runtime.h>
#include <cuda_fp8.h>
#include <cstdint>

// ============================================================================
// y[b,s,o] = 4 * sum_i e4m3(x[b,s,i]*0.5) * W_e4m3[o,i]  + bias[o]
// M = 16384, N = 4096, K = 4096, fp32 out.
// R9: register-slack configuration. CTA 128x128, 512 thr, 16 warps x (32x32),
//     __launch_bounds__(512,2) -> ~62 regs (vs 128 cap), 32 warps/SM.
//     Hypothesis: the alu/fma issue bloat in R4/R6 was ptxas MOV-shuffling of
//     accumulator quads at the 128-reg cap; slack removes it.
// ============================================================================

#define DI __device__ __forceinline__

// ---------------- device scratch --------------------------------------------
__device__ uint8_t g_Aq[16384u * 4096u];   // 64MB quantized activations (e4m3)
__device__ uint8_t g_Wq[4096u * 4096u];    // 16MB weight as e4m3 bytes
__device__ int     g_wflag;                // 1 if weight buffer is fp32

// ---------------- helpers ---------------------------------------------------
DI uint32_t smem_u32(const void* p) {
    uint32_t a;
    asm("{ .reg .u64 t; cvta.to.shared.u64 t, %1; cvt.u32.u64 %0, t; }"
        : "=r"(a) : "l"(p));
    return a;
}
DI void cp_async16(uint32_t dst, const void* src) {
    asm volatile("cp.async.cg.shared.global [%0], [%1], 16;" :: "r"(dst), "l"(src));
}
DI void cp_commit() { asm volatile("cp.async.commit_group;" ::: "memory"); }
template <int N> DI void cp_wait() {
    asm volatile("cp.async.wait_group %0;" :: "n"(N) : "memory");
}
DI void ldmatrix4(uint32_t& r0, uint32_t& r1, uint32_t& r2, uint32_t& r3, uint32_t a) {
    asm volatile("ldmatrix.sync.aligned.m8n8.x4.shared.b16 {%0,%1,%2,%3}, [%4];"
                 : "=r"(r0), "=r"(r1), "=r"(r2), "=r"(r3) : "r"(a));
}
DI void mma_e4m3(float& c0, float& c1, float& c2, float& c3,
                 uint32_t a0, uint32_t a1, uint32_t a2, uint32_t a3,
                 uint32_t b0, uint32_t b1) {
    asm volatile(
        "mma.sync.aligned.m16n8k32.row.col.f32.e4m3.e4m3.f32 "
        "{%0,%1,%2,%3}, {%4,%5,%6,%7}, {%8,%9}, {%0,%1,%2,%3};"
        : "+f"(c0), "+f"(c1), "+f"(c2), "+f"(c3)
        : "r"(a0), "r"(a1), "r"(a2), "r"(a3), "r"(b0), "r"(b1));
}

// ============================================================================
// Kernel 1: quantize activations  e4m3(x * 0.5)
// ============================================================================
__global__ void quant_act(const float4* __restrict__ in, int n4) {
    uint32_t* out = reinterpret_cast<uint32_t*>(g_Aq);
    int i = blockIdx.x * blockDim.x + threadIdx.x;
    int stride = gridDim.x * blockDim.x;
    for (; i < n4; i += stride) {
        float4 v = in[i];
        __nv_fp8x2_storage_t p0 = __nv_cvt_float2_to_fp8x2(
            make_float2(v.x * 0.5f, v.y * 0.5f), __NV_SATFINITE, __NV_E4M3);
        __nv_fp8x2_storage_t p1 = __nv_cvt_float2_to_fp8x2(
            make_float2(v.z * 0.5f, v.w * 0.5f), __NV_SATFINITE, __NV_E4M3);
        out[i] = (uint32_t)p0 | ((uint32_t)p1 << 16);
    }
}

// ============================================================================
// Kernel 2: weight dtype detect + normalize to e4m3 bytes
// ============================================================================
__global__ void detect_wdtype(const float* __restrict__ w) {
    if (blockIdx.x == 0 && threadIdx.x == 0) {
        int ok = 1;
        for (int i = 0; i < 256; i++) {
            float x = w[i];
            if (!(fabsf(x) <= 448.0f)) { ok = 0; break; }
        }
        g_wflag = ok;
    }
}

__global__ void prep_w(const void* __restrict__ w, int n) {
    int flag = g_wflag;
    int idx = blockIdx.x * blockDim.x + threadIdx.x;
    int stride = gridDim.x * blockDim.x;
    if (flag) {
        const float4* wf = (const float4*)w;
        uint32_t* o = reinterpret_cast<uint32_t*>(g_Wq);
        for (int i = idx; i < n / 4; i += stride) {
            float4 v = wf[i];
            __nv_fp8x2_storage_t p0 = __nv_cvt_float2_to_fp8x2(
                make_float2(v.x, v.y), __NV_SATFINITE, __NV_E4M3);
            __nv_fp8x2_storage_t p1 = __nv_cvt_float2_to_fp8x2(
                make_float2(v.z, v.w), __NV_SATFINITE, __NV_E4M3);
            o[i] = (uint32_t)p0 | ((uint32_t)p1 << 16);
        }
    } else {
        const uint4* wb = (const uint4*)w;
        uint4* o = reinterpret_cast<uint4*>(g_Wq);
        for (int i = idx; i < n / 16; i += stride) o[i] = wb[i];
    }
}

// ============================================================================
// Kernel 3: FP8 GEMM
// ============================================================================
#define BM 128
#define BN 128
#define BK 128
#define KDIM 4096
#define NDIM 4096
#define MDIM 16384
#define KCHUNKS (KDIM / BK)          // 32
#define STAGES 3
#define NTHREADS 512

#define A_BYTES (BM * BK)            // 16384
#define B_BYTES (BN * BK)            // 16384
#define STAGE_BYTES (A_BYTES + B_BYTES)   // 32768
#define SM_TOTAL (STAGES * STAGE_BYTES)   // 98304 per CTA

// 512 threads: thread loads 2 A rows + 2 B rows (row stride 64 -> swizzled
// 16B unit is a per-thread constant).
DI void load_stage(uint32_t As, uint32_t Bs,
                   const uint8_t* __restrict__ ag,
                   const uint8_t* __restrict__ bg) {
#pragma unroll
    for (int i = 0; i < BM / 64; i++)
        cp_async16(As + i * (64 * 128), ag + (size_t)i * (64 * KDIM));
#pragma unroll
    for (int i = 0; i < BN / 64; i++)
        cp_async16(Bs + i * (64 * 128), bg + (size_t)i * (64 * KDIM));
}

__global__ void __launch_bounds__(NTHREADS, 2)
gemm_kernel(const float* __restrict__ bias, float* __restrict__ out) {
    extern __shared__ char smem[];
    uint32_t sb = smem_u32(smem);
    int tid = (int)threadIdx.x;
    int wid = tid >> 5;
    int lid = tid & 31;
    int wm = wid & 3;                 // M dir: 4 warps * 32 rows
    int wn = wid >> 2;                // N dir: 4 warps * 32 cols
    int tm = blockIdx.y;
    int tn = blockIdx.x;

    // ---- per-thread constant load addressing ----
    int lcol = tid & 7;
    int lrow = tid >> 3;              // 0..63
    uint32_t aSmBase = (uint32_t)(lrow * 128 + ((lcol ^ (lrow & 7)) << 4));
    uint32_t bSmBase = aSmBase + A_BYTES;
    const uint8_t* ag = g_Aq + ((size_t)(tm * BM + lrow)) * KDIM + lcol * 16;
    const uint8_t* bg = g_Wq + ((size_t)(tn * BN + lrow)) * KDIM + lcol * 16;

    float acc[2][4][4];
#pragma unroll
    for (int mi = 0; mi < 2; mi++)
#pragma unroll
        for (int ni = 0; ni < 4; ni++)
#pragma unroll
            for (int r = 0; r < 4; r++) acc[mi][ni][r] = 0.0f;

    // lane-derived ldmatrix source coordinates (proven R2-R8)
    int a_row_l = (lid & 7) + ((lid >> 3) & 1) * 8;
    int a_half  = lid >> 4;
    int b_row_l = (lid & 7) + ((lid >> 4) & 1) * 8;
    int b_half  = (lid >> 3) & 1;

    uint32_t aOff[2], bOff[2];
#pragma unroll
    for (int mi = 0; mi < 2; mi++) {
        int row = wm * 32 + mi * 16 + a_row_l;
        aOff[mi] = (uint32_t)(row * 128 + ((a_half ^ (row & 7)) << 4));
    }
#pragma unroll
    for (int np = 0; np < 2; np++) {
        int n = wn * 32 + np * 16 + b_row_l;
        bOff[np] = (uint32_t)(n * 128 + ((b_half ^ (n & 7)) << 4)) + A_BYTES;
    }

    // prologue: fill stages 0,1
#pragma unroll
    for (int s = 0; s < STAGES - 1; s++) {
        load_stage(sb + s * STAGE_BYTES + aSmBase, sb + s * STAGE_BYTES + bSmBase,
                   ag, bg);
        cp_commit();
        ag += BK;
        bg += BK;
    }

    int cs = 0;                        // compute stage
    int ps = STAGES - 1;               // produce stage

    for (int ck = 0; ck < KCHUNKS; ck++) {
        cp_wait<STAGES - 2>();
        __syncthreads();
        if (ck + STAGES - 1 < KCHUNKS) {
            load_stage(sb + ps * STAGE_BYTES + aSmBase,
                       sb + ps * STAGE_BYTES + bSmBase, ag, bg);
            ag += BK;
            bg += BK;
            if (++ps == STAGES) ps = 0;
        }
        cp_commit();                  // uniform group accounting

        uint32_t As = sb + cs * STAGE_BYTES;
        if (++cs == STAGES) cs = 0;

#pragma unroll
        for (int ks = 0; ks < 4; ks++) {
            uint32_t x = (uint32_t)(ks << 5);
            uint32_t a[2][4];
            uint32_t b[4][2];
#pragma unroll
            for (int mi = 0; mi < 2; mi++)
                ldmatrix4(a[mi][0], a[mi][1], a[mi][2], a[mi][3],
                          (As + aOff[mi]) ^ x);
#pragma unroll
            for (int np = 0; np < 2; np++)
                ldmatrix4(b[2 * np][0], b[2 * np][1],
                          b[2 * np + 1][0], b[2 * np + 1][1],
                          (As + bOff[np]) ^ x);
#pragma unroll
            for (int mi = 0; mi < 2; mi++)
#pragma unroll
                for (int ni = 0; ni < 4; ni++)
                    mma_e4m3(acc[mi][ni][0], acc[mi][ni][1], acc[mi][ni][2], acc[mi][ni][3],
                             a[mi][0], a[mi][1], a[mi][2], a[mi][3],
                             b[ni][0], b[ni][1]);
        }
    }

    // Epilogue: out = acc*4 + bias
    int qrow = lid >> 2;
    int qcol = (lid & 3) * 2;
    int m0 = tm * BM + wm * 32 + qrow;
    int n0 = tn * BN + wn * 32 + qcol;
#pragma unroll
    for (int mi = 0; mi < 2; mi++) {
#pragma unroll
        for (int ni = 0; ni < 4; ni++) {
            int n = n0 + ni * 8;
            float b0 = __ldg(bias + n);
            float b1 = __ldg(bias + n + 1);
            int mA = m0 + mi * 16;
            int mB = mA + 8;
            float2 v0 = make_float2(acc[mi][ni][0] * 4.0f + b0,
                                    acc[mi][ni][1] * 4.0f + b1);
            float2 v1 = make_float2(acc[mi][ni][2] * 4.0f + b0,
                                    acc[mi][ni][3] * 4.0f + b1);
            *reinterpret_cast<float2*>(out + (size_t)mA * NDIM + n) = v0;
            *reinterpret_cast<float2*>(out + (size_t)mB * NDIM + n) = v1;
        }
    }
}

// ============================================================================
// Host launch
// ============================================================================
extern "C" void kernel_launch(void* const* d_in, const int* in_sizes, int n_in,
                              void* d_out, int out_size) {
    const float* input = nullptr;
    const void*  weight = nullptr;
    const float* bias = nullptr;
    for (int i = 0; i < n_in; i++) {
        if (in_sizes[i] == 4 * 4096 * 4096)  input = (const float*)d_in[i];
        else if (in_sizes[i] == 4096 * 4096) weight = d_in[i];
        else if (in_sizes[i] == 4096)        bias = (const float*)d_in[i];
    }
    if (!input)  input  = (const float*)d_in[0];
    if (!weight) weight = d_in[1];
    if (!bias)   bias   = (const float*)d_in[2];
    float* out = (float*)d_out;

    int n4 = (4 * 4096 * 4096) / 4;
    quant_act<<<8192, 256>>>((const float4*)input, n4);

    detect_wdtype<<<1, 1>>>((const float*)weight);
    prep_w<<<2048, 256>>>(weight, 4096 * 4096);

    static bool attr_set = false;
    if (!attr_set) {
        cudaFuncSetAttribute(gemm_kernel,
                             cudaFuncAttributeMaxDynamicSharedMemorySize, SM_TOTAL);
        attr_set = true;
    }
    dim3 grid(NDIM / BN, MDIM / BM);   // (32, 128)
    gemm_kernel<<<grid, NTHREADS, SM_TOTAL>>>(bias, out);
}

// round 11
// speedup vs baseline: 1.4584x; 1.4584x over previous
#include <cuda_runtime.h>
#include <cuda_fp8.h>
#include <cuda_bf16.h>
#include <cstdint>

// ============================================================================
// y[b,s,o] = 4 * sum_i e4m3(x[b,s,i]*0.5) * W_e4m3[o,i]  + bias[o]
// M = 16384, N = 4096, K = 4096, fp32 out.
// R10: R6 structure, but operands stored as BF16 (e4m3 -> bf16 is EXACT) and
//      the MMA is native bf16 HMMA m16n8k16 (no fp8-mma legalization ALU).
//      128B smem rows now hold K=64 bf16 -> identical swizzle/ldmatrix maps,
//      identical 32KB stages; KCHUNKS 32 -> 64.
// ============================================================================

#define DI __device__ __forceinline__

// ---------------- device scratch (bytes; bf16 payload) ----------------------
__device__ uint8_t g_Aq[16384u * 4096u * 2u];   // 128MB activations bf16
__device__ uint8_t g_Wq[4096u * 4096u * 2u];    // 32MB weights bf16
__device__ int     g_wflag;                     // 1 if weight buffer is fp32

// ---------------- helpers ---------------------------------------------------
DI uint32_t smem_u32(const void* p) {
    uint32_t a;
    asm("{ .reg .u64 t; cvta.to.shared.u64 t, %1; cvt.u32.u64 %0, t; }"
        : "=r"(a) : "l"(p));
    return a;
}
DI void cp_async16(uint32_t dst, const void* src) {
    asm volatile("cp.async.cg.shared.global [%0], [%1], 16;" :: "r"(dst), "l"(src));
}
DI void cp_commit() { asm volatile("cp.async.commit_group;" ::: "memory"); }
template <int N> DI void cp_wait() {
    asm volatile("cp.async.wait_group %0;" :: "n"(N) : "memory");
}
DI void ldmatrix4(uint32_t& r0, uint32_t& r1, uint32_t& r2, uint32_t& r3, uint32_t a) {
    asm volatile("ldmatrix.sync.aligned.m8n8.x4.shared.b16 {%0,%1,%2,%3}, [%4];"
                 : "=r"(r0), "=r"(r1), "=r"(r2), "=r"(r3) : "r"(a));
}
DI void mma_bf16(float& c0, float& c1, float& c2, float& c3,
                 uint32_t a0, uint32_t a1, uint32_t a2, uint32_t a3,
                 uint32_t b0, uint32_t b1) {
    asm volatile(
        "mma.sync.aligned.m16n8k16.row.col.f32.bf16.bf16.f32 "
        "{%0,%1,%2,%3}, {%4,%5,%6,%7}, {%8,%9}, {%0,%1,%2,%3};"
        : "+f"(c0), "+f"(c1), "+f"(c2), "+f"(c3)
        : "r"(a0), "r"(a1), "r"(a2), "r"(a3), "r"(b0), "r"(b1));
}

// e4m3 quantize (x*0.5, satfinite) then EXACT widen to bf16
DI __nv_bfloat16 qdq_bf16(float x) {
    __nv_fp8_storage_t q = __nv_cvt_float_to_fp8(x * 0.5f, __NV_SATFINITE, __NV_E4M3);
    float f = __half2float(__nv_cvt_fp8_to_halfraw(q, __NV_E4M3));   // exact
    return __float2bfloat16(f);                                       // exact
}
DI __nv_bfloat16 e4m3_bf16(uint8_t b) {
    float f = __half2float(__nv_cvt_fp8_to_halfraw((__nv_fp8_storage_t)b, __NV_E4M3));
    return __float2bfloat16(f);
}

// ============================================================================
// Kernel 1: quantize activations -> bf16(e4m3(x*0.5))
// ============================================================================
__global__ void quant_act(const float4* __restrict__ in, int n4) {
    uint2* out = reinterpret_cast<uint2*>(g_Aq);
    int i = blockIdx.x * blockDim.x + threadIdx.x;
    int stride = gridDim.x * blockDim.x;
    for (; i < n4; i += stride) {
        float4 v = in[i];
        __nv_bfloat162 p0 = __nv_bfloat162(qdq_bf16(v.x), qdq_bf16(v.y));
        __nv_bfloat162 p1 = __nv_bfloat162(qdq_bf16(v.z), qdq_bf16(v.w));
        uint2 o;
        o.x = *reinterpret_cast<uint32_t*>(&p0);
        o.y = *reinterpret_cast<uint32_t*>(&p1);
        out[i] = o;
    }
}

// ============================================================================
// Kernel 2: weight dtype detect + normalize to bf16
// ============================================================================
__global__ void detect_wdtype(const float* __restrict__ w) {
    if (blockIdx.x == 0 && threadIdx.x == 0) {
        int ok = 1;
        for (int i = 0; i < 256; i++) {
            float x = w[i];
            if (!(fabsf(x) <= 448.0f)) { ok = 0; break; }
        }
        g_wflag = ok;
    }
}

__global__ void prep_w(const void* __restrict__ w, int n) {
    int flag = g_wflag;
    int idx = blockIdx.x * blockDim.x + threadIdx.x;
    int stride = gridDim.x * blockDim.x;
    __nv_bfloat16* o = reinterpret_cast<__nv_bfloat16*>(g_Wq);
    if (flag) {
        const float4* wf = (const float4*)w;
        for (int i = idx; i < n / 4; i += stride) {
            float4 v = wf[i];
            // fp32 -> e4m3 (exact storage round-trip of reference) -> bf16
            o[i * 4 + 0] = e4m3_bf16(__nv_cvt_float_to_fp8(v.x, __NV_SATFINITE, __NV_E4M3));
            o[i * 4 + 1] = e4m3_bf16(__nv_cvt_float_to_fp8(v.y, __NV_SATFINITE, __NV_E4M3));
            o[i * 4 + 2] = e4m3_bf16(__nv_cvt_float_to_fp8(v.z, __NV_SATFINITE, __NV_E4M3));
            o[i * 4 + 3] = e4m3_bf16(__nv_cvt_float_to_fp8(v.w, __NV_SATFINITE, __NV_E4M3));
        }
    } else {
        const uchar4* wb = (const uchar4*)w;
        for (int i = idx; i < n / 4; i += stride) {
            uchar4 v = wb[i];
            o[i * 4 + 0] = e4m3_bf16(v.x);
            o[i * 4 + 1] = e4m3_bf16(v.y);
            o[i * 4 + 2] = e4m3_bf16(v.z);
            o[i * 4 + 3] = e4m3_bf16(v.w);
        }
    }
}

// ============================================================================
// Kernel 3: BF16 GEMM (native HMMA)
// ============================================================================
#define BM 128
#define BN 128
#define KDIM 4096
#define KBYTES 8192                  // row stride in bytes (4096 bf16)
#define BKB 128                      // chunk bytes per row = 64 bf16
#define NDIM 4096
#define MDIM 16384
#define KCHUNKS 64                   // 4096 / 64
#define STAGES 3
#define NTHREADS 256

#define A_BYTES (BM * 128)           // 16384
#define B_BYTES (BN * 128)           // 16384
#define STAGE_BYTES (A_BYTES + B_BYTES)   // 32768
#define SM_TOTAL (STAGES * STAGE_BYTES)   // 98304 per CTA

// thread loads 4 A rows + 4 B rows (rows stride 32 -> swizzled unit constant)
DI void load_stage(uint32_t As, uint32_t Bs,
                   const uint8_t* __restrict__ ag,
                   const uint8_t* __restrict__ bg) {
#pragma unroll
    for (int i = 0; i < BM / 32; i++)
        cp_async16(As + i * (32 * 128), ag + (size_t)i * (32 * KBYTES));
#pragma unroll
    for (int i = 0; i < BN / 32; i++)
        cp_async16(Bs + i * (32 * 128), bg + (size_t)i * (32 * KBYTES));
}

__global__ void __launch_bounds__(NTHREADS, 2)
gemm_kernel(const float* __restrict__ bias, float* __restrict__ out) {
    extern __shared__ char smem[];
    uint32_t sb = smem_u32(smem);
    int tid = (int)threadIdx.x;
    int wid = tid >> 5;
    int lid = tid & 31;
    int wm = wid & 1;                 // M dir: 2 warps * 64 rows
    int wn = wid >> 1;                // N dir: 4 warps * 32 cols
    int tm = blockIdx.y;
    int tn = blockIdx.x;

    // ---- per-thread constant load addressing ----
    int lcol = tid & 7;
    int lrow = tid >> 3;              // 0..31
    uint32_t aSmBase = (uint32_t)(lrow * 128 + ((lcol ^ (lrow & 7)) << 4));
    uint32_t bSmBase = aSmBase + A_BYTES;
    const uint8_t* ag = g_Aq + ((size_t)(tm * BM + lrow)) * KBYTES + lcol * 16;
    const uint8_t* bg = g_Wq + ((size_t)(tn * BN + lrow)) * KBYTES + lcol * 16;

    float acc[4][4][4];
#pragma unroll
    for (int mi = 0; mi < 4; mi++)
#pragma unroll
        for (int ni = 0; ni < 4; ni++)
#pragma unroll
            for (int r = 0; r < 4; r++) acc[mi][ni][r] = 0.0f;

    // lane-derived ldmatrix source coordinates (proven R2-R9; b16-native)
    int a_row_l = (lid & 7) + ((lid >> 3) & 1) * 8;
    int a_half  = lid >> 4;
    int b_row_l = (lid & 7) + ((lid >> 4) & 1) * 8;
    int b_half  = (lid >> 3) & 1;

    uint32_t aOff[4], bOff[2];
#pragma unroll
    for (int mi = 0; mi < 4; mi++) {
        int row = wm * 64 + mi * 16 + a_row_l;
        aOff[mi] = (uint32_t)(row * 128 + ((a_half ^ (row & 7)) << 4));
    }
#pragma unroll
    for (int np = 0; np < 2; np++) {
        int n = wn * 32 + np * 16 + b_row_l;
        bOff[np] = (uint32_t)(n * 128 + ((b_half ^ (n & 7)) << 4)) + A_BYTES;
    }

    // prologue: fill stages 0,1
#pragma unroll
    for (int s = 0; s < STAGES - 1; s++) {
        load_stage(sb + s * STAGE_BYTES + aSmBase, sb + s * STAGE_BYTES + bSmBase,
                   ag, bg);
        cp_commit();
        ag += BKB;
        bg += BKB;
    }

    uint32_t a[2][4][4];
    uint32_t b[2][4][2];
    int cs = 0;                        // compute stage
    int ps = STAGES - 1;               // produce stage

    for (int ck = 0; ck < KCHUNKS; ck++) {
        cp_wait<STAGES - 2>();
        __syncthreads();
        if (ck + STAGES - 1 < KCHUNKS) {
            load_stage(sb + ps * STAGE_BYTES + aSmBase,
                       sb + ps * STAGE_BYTES + bSmBase, ag, bg);
            ag += BKB;
            bg += BKB;
            if (++ps == STAGES) ps = 0;
        }
        cp_commit();                  // uniform group accounting

        uint32_t As = sb + cs * STAGE_BYTES;
        if (++cs == STAGES) cs = 0;

        uint32_t aB[4], bB[2];
#pragma unroll
        for (int mi = 0; mi < 4; mi++) aB[mi] = As + aOff[mi];
#pragma unroll
        for (int np = 0; np < 2; np++) bB[np] = As + bOff[np];

        // preload ks = 0 fragments (k16 = 32B = 2x16B units)
#pragma unroll
        for (int mi = 0; mi < 4; mi++)
            ldmatrix4(a[0][mi][0], a[0][mi][1], a[0][mi][2], a[0][mi][3], aB[mi]);
#pragma unroll
        for (int np = 0; np < 2; np++)
            ldmatrix4(b[0][2 * np][0], b[0][2 * np][1],
                      b[0][2 * np + 1][0], b[0][2 * np + 1][1], bB[np]);

#pragma unroll
        for (int ks = 0; ks < 4; ks++) {   // 4 x k16 within 64-elem chunk
            int cur = ks & 1;
            int nxt = cur ^ 1;
            if (ks < 3) {
                uint32_t x = (uint32_t)((ks + 1) << 5);
#pragma unroll
                for (int mi = 0; mi < 4; mi++)
                    ldmatrix4(a[nxt][mi][0], a[nxt][mi][1], a[nxt][mi][2], a[nxt][mi][3],
                              aB[mi] ^ x);
#pragma unroll
                for (int np = 0; np < 2; np++)
                    ldmatrix4(b[nxt][2 * np][0], b[nxt][2 * np][1],
                              b[nxt][2 * np + 1][0], b[nxt][2 * np + 1][1],
                              bB[np] ^ x);
            }
#pragma unroll
            for (int mi = 0; mi < 4; mi++)
#pragma unroll
                for (int ni = 0; ni < 4; ni++)
                    mma_bf16(acc[mi][ni][0], acc[mi][ni][1], acc[mi][ni][2], acc[mi][ni][3],
                             a[cur][mi][0], a[cur][mi][1], a[cur][mi][2], a[cur][mi][3],
                             b[cur][ni][0], b[cur][ni][1]);
        }
    }

    // Epilogue: out = acc*4 + bias
    int qrow = lid >> 2;
    int qcol = (lid & 3) * 2;
    int m0 = tm * BM + wm * 64 + qrow;
    int n0 = tn * BN + wn * 32 + qcol;
#pragma unroll
    for (int mi = 0; mi < 4; mi++) {
#pragma unroll
        for (int ni = 0; ni < 4; ni++) {
            int n = n0 + ni * 8;
            float b0 = __ldg(bias + n);
            float b1 = __ldg(bias + n + 1);
            int mA = m0 + mi * 16;
            int mB = mA + 8;
            float2 v0 = make_float2(acc[mi][ni][0] * 4.0f + b0,
                                    acc[mi][ni][1] * 4.0f + b1);
            float2 v1 = make_float2(acc[mi][ni][2] * 4.0f + b0,
                                    acc[mi][ni][3] * 4.0f + b1);
            *reinterpret_cast<float2*>(out + (size_t)mA * NDIM + n) = v0;
            *reinterpret_cast<float2*>(out + (size_t)mB * NDIM + n) = v1;
        }
    }
}

// ============================================================================
// Host launch
// ============================================================================
extern "C" void kernel_launch(void* const* d_in, const int* in_sizes, int n_in,
                              void* d_out, int out_size) {
    const float* input = nullptr;
    const void*  weight = nullptr;
    const float* bias = nullptr;
    for (int i = 0; i < n_in; i++) {
        if (in_sizes[i] == 4 * 4096 * 4096)  input = (const float*)d_in[i];
        else if (in_sizes[i] == 4096 * 4096) weight = d_in[i];
        else if (in_sizes[i] == 4096)        bias = (const float*)d_in[i];
    }
    if (!input)  input  = (const float*)d_in[0];
    if (!weight) weight = d_in[1];
    if (!bias)   bias   = (const float*)d_in[2];
    float* out = (float*)d_out;

    int n4 = (4 * 4096 * 4096) / 4;
    quant_act<<<8192, 256>>>((const float4*)input, n4);

    detect_wdtype<<<1, 1>>>((const float*)weight);
    prep_w<<<2048, 256>>>(weight, 4096 * 4096);

    static bool attr_set = false;
    if (!attr_set) {
        cudaFuncSetAttribute(gemm_kernel,
                             cudaFuncAttributeMaxDynamicSharedMemorySize, SM_TOTAL);
        attr_set = true;
    }
    dim3 grid(NDIM / BN, MDIM / BM);   // (32, 128)
    gemm_kernel<<<grid, NTHREADS, SM_TOTAL>>>(bias, out);
}

// round 13
// speedup vs baseline: 1.5003x; 1.0287x over previous
#include <cuda_runtime.h>
#include <cuda_fp8.h>
#include <cuda_bf16.h>
#include <cstdint>

// ============================================================================
// y[b,s,o] = 4 * sum_i e4m3(x[b,s,i]*0.5) * W_e4m3[o,i]  + bias[o]
// M = 16384, N = 4096, K = 4096, fp32 out.
// R13: R12's cross-chunk ks0 preload with the visibility race CLOSED:
//   chunk top = sync1 -> prefetch -> commit -> wait<1> -> sync2.
//   sync2 makes every thread's wait (own-group completion) a GLOBAL guarantee,
//   so reading next-stage data written by other threads' cp.asyncs is safe.
// ============================================================================

#define DI __device__ __forceinline__

// ---------------- device scratch (bytes; bf16 payload) ----------------------
__device__ uint8_t g_Aq[16384u * 4096u * 2u];   // 128MB activations bf16
__device__ uint8_t g_Wq[4096u * 4096u * 2u];    // 32MB weights bf16
__device__ int     g_wflag;                     // 1 if weight buffer is fp32

// ---------------- helpers ---------------------------------------------------
DI uint32_t smem_u32(const void* p) {
    uint32_t a;
    asm("{ .reg .u64 t; cvta.to.shared.u64 t, %1; cvt.u32.u64 %0, t; }"
        : "=r"(a) : "l"(p));
    return a;
}
DI void cp_async16(uint32_t dst, const void* src) {
    asm volatile("cp.async.cg.shared.global [%0], [%1], 16;" :: "r"(dst), "l"(src));
}
DI void cp_commit() { asm volatile("cp.async.commit_group;" ::: "memory"); }
template <int N> DI void cp_wait() {
    asm volatile("cp.async.wait_group %0;" :: "n"(N) : "memory");
}
DI void ldmatrix4(uint32_t& r0, uint32_t& r1, uint32_t& r2, uint32_t& r3, uint32_t a) {
    asm volatile("ldmatrix.sync.aligned.m8n8.x4.shared.b16 {%0,%1,%2,%3}, [%4];"
                 : "=r"(r0), "=r"(r1), "=r"(r2), "=r"(r3) : "r"(a));
}
DI void mma_bf16(float& c0, float& c1, float& c2, float& c3,
                 uint32_t a0, uint32_t a1, uint32_t a2, uint32_t a3,
                 uint32_t b0, uint32_t b1) {
    asm volatile(
        "mma.sync.aligned.m16n8k16.row.col.f32.bf16.bf16.f32 "
        "{%0,%1,%2,%3}, {%4,%5,%6,%7}, {%8,%9}, {%0,%1,%2,%3};"
        : "+f"(c0), "+f"(c1), "+f"(c2), "+f"(c3)
        : "r"(a0), "r"(a1), "r"(a2), "r"(a3), "r"(b0), "r"(b1));
}

// e4m3 quantize (x*0.5, satfinite) then EXACT widen to bf16
DI __nv_bfloat16 qdq_bf16(float x) {
    __nv_fp8_storage_t q = __nv_cvt_float_to_fp8(x * 0.5f, __NV_SATFINITE, __NV_E4M3);
    float f = __half2float(__nv_cvt_fp8_to_halfraw(q, __NV_E4M3));   // exact
    return __float2bfloat16(f);                                       // exact
}
DI __nv_bfloat16 e4m3_bf16(uint8_t b) {
    float f = __half2float(__nv_cvt_fp8_to_halfraw((__nv_fp8_storage_t)b, __NV_E4M3));
    return __float2bfloat16(f);
}

// ============================================================================
// Kernel 1: quantize activations -> bf16(e4m3(x*0.5))
// ============================================================================
__global__ void quant_act(const float4* __restrict__ in, int n4) {
    uint2* out = reinterpret_cast<uint2*>(g_Aq);
    int i = blockIdx.x * blockDim.x + threadIdx.x;
    int stride = gridDim.x * blockDim.x;
    for (; i < n4; i += stride) {
        float4 v = in[i];
        __nv_bfloat162 p0 = __nv_bfloat162(qdq_bf16(v.x), qdq_bf16(v.y));
        __nv_bfloat162 p1 = __nv_bfloat162(qdq_bf16(v.z), qdq_bf16(v.w));
        uint2 o;
        o.x = *reinterpret_cast<uint32_t*>(&p0);
        o.y = *reinterpret_cast<uint32_t*>(&p1);
        out[i] = o;
    }
}

// ============================================================================
// Kernel 2: weight dtype detect + normalize to bf16
// ============================================================================
__global__ void detect_wdtype(const float* __restrict__ w) {
    if (blockIdx.x == 0 && threadIdx.x == 0) {
        int ok = 1;
        for (int i = 0; i < 256; i++) {
            float x = w[i];
            if (!(fabsf(x) <= 448.0f)) { ok = 0; break; }
        }
        g_wflag = ok;
    }
}

__global__ void prep_w(const void* __restrict__ w, int n) {
    int flag = g_wflag;
    int idx = blockIdx.x * blockDim.x + threadIdx.x;
    int stride = gridDim.x * blockDim.x;
    __nv_bfloat16* o = reinterpret_cast<__nv_bfloat16*>(g_Wq);
    if (flag) {
        const float4* wf = (const float4*)w;
        for (int i = idx; i < n / 4; i += stride) {
            float4 v = wf[i];
            o[i * 4 + 0] = e4m3_bf16(__nv_cvt_float_to_fp8(v.x, __NV_SATFINITE, __NV_E4M3));
            o[i * 4 + 1] = e4m3_bf16(__nv_cvt_float_to_fp8(v.y, __NV_SATFINITE, __NV_E4M3));
            o[i * 4 + 2] = e4m3_bf16(__nv_cvt_float_to_fp8(v.z, __NV_SATFINITE, __NV_E4M3));
            o[i * 4 + 3] = e4m3_bf16(__nv_cvt_float_to_fp8(v.w, __NV_SATFINITE, __NV_E4M3));
        }
    } else {
        const uchar4* wb = (const uchar4*)w;
        for (int i = idx; i < n / 4; i += stride) {
            uchar4 v = wb[i];
            o[i * 4 + 0] = e4m3_bf16(v.x);
            o[i * 4 + 1] = e4m3_bf16(v.y);
            o[i * 4 + 2] = e4m3_bf16(v.z);
            o[i * 4 + 3] = e4m3_bf16(v.w);
        }
    }
}

// ============================================================================
// Kernel 3: BF16 GEMM (native HMMA)
// ============================================================================
#define BM 128
#define BN 128
#define KBYTES 8192                  // row stride (4096 bf16)
#define BKB 128                      // chunk bytes per row = 64 bf16
#define NDIM 4096
#define MDIM 16384
#define KCHUNKS 64
#define STAGES 3
#define NTHREADS 256

#define A_BYTES (BM * 128)           // 16384
#define B_BYTES (BN * 128)           // 16384
#define STAGE_BYTES (A_BYTES + B_BYTES)   // 32768
#define SM_TOTAL (STAGES * STAGE_BYTES)   // 98304 per CTA

// thread loads 4 A rows + 4 B rows (rows stride 32 -> swizzled unit constant)
DI void load_stage(uint32_t As, uint32_t Bs,
                   const uint8_t* __restrict__ ag,
                   const uint8_t* __restrict__ bg) {
#pragma unroll
    for (int i = 0; i < BM / 32; i++)
        cp_async16(As + i * (32 * 128), ag + (size_t)i * (32 * KBYTES));
#pragma unroll
    for (int i = 0; i < BN / 32; i++)
        cp_async16(Bs + i * (32 * 128), bg + (size_t)i * (32 * KBYTES));
}

__global__ void __launch_bounds__(NTHREADS, 2)
gemm_kernel(const float* __restrict__ bias, float* __restrict__ out) {
    extern __shared__ char smem[];
    uint32_t sb = smem_u32(smem);
    int tid = (int)threadIdx.x;
    int wid = tid >> 5;
    int lid = tid & 31;
    int wm = wid & 1;                 // M dir: 2 warps * 64 rows
    int wn = wid >> 1;                // N dir: 4 warps * 32 cols
    int tm = blockIdx.y;
    int tn = blockIdx.x;

    // ---- per-thread constant load addressing ----
    int lcol = tid & 7;
    int lrow = tid >> 3;              // 0..31
    uint32_t aSmBase = (uint32_t)(lrow * 128 + ((lcol ^ (lrow & 7)) << 4));
    uint32_t bSmBase = aSmBase + A_BYTES;
    const uint8_t* ag = g_Aq + ((size_t)(tm * BM + lrow)) * KBYTES + lcol * 16;
    const uint8_t* bg = g_Wq + ((size_t)(tn * BN + lrow)) * KBYTES + lcol * 16;

    float acc[4][4][4];
#pragma unroll
    for (int mi = 0; mi < 4; mi++)
#pragma unroll
        for (int ni = 0; ni < 4; ni++)
#pragma unroll
            for (int r = 0; r < 4; r++) acc[mi][ni][r] = 0.0f;

    // lane-derived ldmatrix source coordinates (proven R2-R11)
    int a_row_l = (lid & 7) + ((lid >> 3) & 1) * 8;
    int a_half  = lid >> 4;
    int b_row_l = (lid & 7) + ((lid >> 4) & 1) * 8;
    int b_half  = (lid >> 3) & 1;

    uint32_t aOff[4], bOff[2];
#pragma unroll
    for (int mi = 0; mi < 4; mi++) {
        int row = wm * 64 + mi * 16 + a_row_l;
        aOff[mi] = (uint32_t)(row * 128 + ((a_half ^ (row & 7)) << 4));
    }
#pragma unroll
    for (int np = 0; np < 2; np++) {
        int n = wn * 32 + np * 16 + b_row_l;
        bOff[np] = (uint32_t)(n * 128 + ((b_half ^ (n & 7)) << 4)) + A_BYTES;
    }

    // prologue: fill stages 0,1 (chunks 0,1)
#pragma unroll
    for (int s = 0; s < STAGES - 1; s++) {
        load_stage(sb + s * STAGE_BYTES + aSmBase, sb + s * STAGE_BYTES + bSmBase,
                   ag, bg);
        cp_commit();
        ag += BKB;
        bg += BKB;
    }

    uint32_t a[2][4][4];
    uint32_t b[2][4][2];
    int cs = 0;                        // compute stage (chunk ck)
    int ps = STAGES - 1;               // produce stage (chunk ck+2)
    bool primed = false;               // ks0 fragments already loaded?

    for (int ck = 0; ck < KCHUNKS; ck++) {
        // ---- chunk top: sync1 -> prefetch -> commit -> wait<1> -> sync2 ----
        __syncthreads();               // 1: all reads of stage ps done
        if (ck + STAGES - 1 < KCHUNKS) {
            load_stage(sb + ps * STAGE_BYTES + aSmBase,
                       sb + ps * STAGE_BYTES + bSmBase, ag, bg);
            ag += BKB;
            bg += BKB;
        }
        cp_commit();
        if (++ps == STAGES) ps = 0;
        cp_wait<STAGES - 2>();         // own G(ck+1) complete
        __syncthreads();               // 2: ALL threads' G(ck+1) complete

        uint32_t As = sb + cs * STAGE_BYTES;
        int cs1 = cs + 1; if (cs1 == STAGES) cs1 = 0;
        uint32_t AsNext = sb + cs1 * STAGE_BYTES;   // globally resident now
        cs = cs1;

        if (!primed) {                 // first chunk only: serial ks0 preload
#pragma unroll
            for (int mi = 0; mi < 4; mi++)
                ldmatrix4(a[0][mi][0], a[0][mi][1], a[0][mi][2], a[0][mi][3],
                          As + aOff[mi]);
#pragma unroll
            for (int np = 0; np < 2; np++)
                ldmatrix4(b[0][2 * np][0], b[0][2 * np][1],
                          b[0][2 * np + 1][0], b[0][2 * np + 1][1],
                          As + bOff[np]);
            primed = true;
        }

#pragma unroll
        for (int ks = 0; ks < 4; ks++) {
            int cur = ks & 1;
            int nxt = cur ^ 1;
            if (ks < 3) {
                uint32_t x = (uint32_t)((ks + 1) << 5);
#pragma unroll
                for (int mi = 0; mi < 4; mi++)
                    ldmatrix4(a[nxt][mi][0], a[nxt][mi][1], a[nxt][mi][2], a[nxt][mi][3],
                              (As + aOff[mi]) ^ x);
#pragma unroll
                for (int np = 0; np < 2; np++)
                    ldmatrix4(b[nxt][2 * np][0], b[nxt][2 * np][1],
                              b[nxt][2 * np + 1][0], b[nxt][2 * np + 1][1],
                              (As + bOff[np]) ^ x);
            } else if (ck + 1 < KCHUNKS) {
                // preload NEXT chunk's ks0 (stage cs1; safe per sync2)
#pragma unroll
                for (int mi = 0; mi < 4; mi++)
                    ldmatrix4(a[nxt][mi][0], a[nxt][mi][1], a[nxt][mi][2], a[nxt][mi][3],
                              AsNext + aOff[mi]);
#pragma unroll
                for (int np = 0; np < 2; np++)
                    ldmatrix4(b[nxt][2 * np][0], b[nxt][2 * np][1],
                              b[nxt][2 * np + 1][0], b[nxt][2 * np + 1][1],
                              AsNext + bOff[np]);
            }
#pragma unroll
            for (int mi = 0; mi < 4; mi++)
#pragma unroll
                for (int ni = 0; ni < 4; ni++)
                    mma_bf16(acc[mi][ni][0], acc[mi][ni][1], acc[mi][ni][2], acc[mi][ni][3],
                             a[cur][mi][0], a[cur][mi][1], a[cur][mi][2], a[cur][mi][3],
                             b[cur][ni][0], b[cur][ni][1]);
        }
    }

    // Epilogue: out = acc*4 + bias
    int qrow = lid >> 2;
    int qcol = (lid & 3) * 2;
    int m0 = tm * BM + wm * 64 + qrow;
    int n0 = tn * BN + wn * 32 + qcol;
#pragma unroll
    for (int mi = 0; mi < 4; mi++) {
#pragma unroll
        for (int ni = 0; ni < 4; ni++) {
            int n = n0 + ni * 8;
            float b0 = __ldg(bias + n);
            float b1 = __ldg(bias + n + 1);
            int mA = m0 + mi * 16;
            int mB = mA + 8;
            float2 v0 = make_float2(acc[mi][ni][0] * 4.0f + b0,
                                    acc[mi][ni][1] * 4.0f + b1);
            float2 v1 = make_float2(acc[mi][ni][2] * 4.0f + b0,
                                    acc[mi][ni][3] * 4.0f + b1);
            *reinterpret_cast<float2*>(out + (size_t)mA * NDIM + n) = v0;
            *reinterpret_cast<float2*>(out + (size_t)mB * NDIM + n) = v1;
        }
    }
}

// ============================================================================
// Host launch
// ============================================================================
extern "C" void kernel_launch(void* const* d_in, const int* in_sizes, int n_in,
                              void* d_out, int out_size) {
    const float* input = nullptr;
    const void*  weight = nullptr;
    const float* bias = nullptr;
    for (int i = 0; i < n_in; i++) {
        if (in_sizes[i] == 4 * 4096 * 4096)  input = (const float*)d_in[i];
        else if (in_sizes[i] == 4096 * 4096) weight = d_in[i];
        else if (in_sizes[i] == 4096)        bias = (const float*)d_in[i];
    }
    if (!input)  input  = (const float*)d_in[0];
    if (!weight) weight = d_in[1];
    if (!bias)   bias   = (const float*)d_in[2];
    float* out = (float*)d_out;

    int n4 = (4 * 4096 * 4096) / 4;
    quant_act<<<8192, 256>>>((const float4*)input, n4);

    detect_wdtype<<<1, 1>>>((const float*)weight);
    prep_w<<<2048, 256>>>(weight, 4096 * 4096);

    static bool attr_set = false;
    if (!attr_set) {
        cudaFuncSetAttribute(gemm_kernel,
                             cudaFuncAttributeMaxDynamicSharedMemorySize, SM_TOTAL);
        attr_set = true;
    }
    dim3 grid(NDIM / BN, MDIM / BM);   // (32, 128)
    gemm_kernel<<<grid, NTHREADS, SM_TOTAL>>>(bias, out);
}